// round 5
// baseline (speedup 1.0000x reference)
#include <cuda_runtime.h>
#include <cuda_fp16.h>
#include <cstdint>

// ============================================================================
// Problem dims (fixed): x [4,2048,1024], E=8 experts, H=4096
// ============================================================================
static constexpr int NTOK = 8192;   // B*T
static constexpr int C    = 1024;
static constexpr int H    = 4096;
static constexpr int E    = 8;

// ============================================================================
// Scratch (static __device__ — no allocation allowed)
// ============================================================================
__device__ __half g_w1t[(size_t)E * H * C];   // [E][H][C]  (N rows, K contiguous)
__device__ __half g_w2t[(size_t)E * C * H];   // [E][C][H]
__device__ __half g_Xg [(size_t)NTOK * C];    // gathered tokens, fp16
__device__ __half g_Hg [(size_t)NTOK * H];    // hidden activations, fp16
__device__ int    g_top1[NTOK];
__device__ int    g_tokof[NTOK];
__device__ int    g_counts[E];
__device__ int    g_offsets[E];
__device__ int    g_cursors[E];

#define DI __device__ __forceinline__

DI uint32_t smem_u32(const void* p) {
    uint32_t r;
    asm("{ .reg .u64 t; cvta.to.shared.u64 t, %1; cvt.u32.u64 %0, t; }"
        : "=r"(r) : "l"(p));
    return r;
}

// 16B async copy, zero-fill when srcsize==0
DI void cp16(uint32_t dst, const void* src, int srcsize) {
    asm volatile("cp.async.cg.shared.global [%0], [%1], 16, %2;"
                 :: "r"(dst), "l"(src), "r"(srcsize) : "memory");
}
#define CP_COMMIT() asm volatile("cp.async.commit_group;" ::: "memory")
#define CP_WAIT(n)  asm volatile("cp.async.wait_group %0;" :: "n"(n) : "memory")

DI void ldsm4(uint32_t* r, uint32_t addr) {
    asm volatile("ldmatrix.sync.aligned.m8n8.x4.shared.b16 {%0,%1,%2,%3}, [%4];"
                 : "=r"(r[0]), "=r"(r[1]), "=r"(r[2]), "=r"(r[3]) : "r"(addr));
}

DI void mma16816(float* d, const uint32_t* a, uint32_t b0, uint32_t b1) {
    asm volatile(
        "mma.sync.aligned.m16n8k16.row.col.f32.f16.f16.f32 "
        "{%0,%1,%2,%3}, {%4,%5,%6,%7}, {%8,%9}, {%0,%1,%2,%3};"
        : "+f"(d[0]), "+f"(d[1]), "+f"(d[2]), "+f"(d[3])
        : "r"(a[0]), "r"(a[1]), "r"(a[2]), "r"(a[3]), "r"(b0), "r"(b1));
}

// 128B tile rows (64 halves), 8x16B chunks; chunk ^= row&7 -> ldmatrix phases
// and cp.async stores are bank-conflict-free.
DI uint32_t swz(int row, int chunk) {
    return (uint32_t)(row * 128 + ((chunk ^ (row & 7)) << 4));
}

// ============================================================================
// Stage 1: setup kernels
// ============================================================================

// fp32 [R][Cc] (per expert, row-major) -> fp16 transposed [Cc][R]
// WHICH==0 also zeroes the expert counters (fused k_zero).
template<int WHICH>
__global__ void k_transpose(const float* __restrict__ in) {
    constexpr int R  = (WHICH == 0) ? C : H;
    constexpr int Cc = (WHICH == 0) ? H : C;
    __half* outb = (WHICH == 0) ? g_w1t : g_w2t;
    if (WHICH == 0 && blockIdx.x == 0 && blockIdx.y == 0 && blockIdx.z == 0 &&
        threadIdx.y == 0 && threadIdx.x < E)
        g_counts[threadIdx.x] = 0;
    __shared__ float t[32][33];
    const size_t mat = (size_t)R * Cc;
    const float* src = in + (size_t)blockIdx.z * mat;
    __half* dst = outb + (size_t)blockIdx.z * mat;
    const int c0 = blockIdx.x * 32, r0 = blockIdx.y * 32;
    const int tx = threadIdx.x, ty = threadIdx.y;
    #pragma unroll
    for (int i = 0; i < 32; i += 8)
        t[ty + i][tx] = src[(size_t)(r0 + ty + i) * Cc + c0 + tx];
    __syncthreads();
    #pragma unroll
    for (int i = 0; i < 32; i += 8)
        dst[(size_t)(c0 + ty + i) * R + r0 + tx] = __float2half(t[tx][ty + i]);
}

// Router + histogram: one warp per token. argmax(logits)==argmax(softmax).
__global__ void k_router(const float* __restrict__ x,
                         const float* __restrict__ wr,
                         const float* __restrict__ br) {
    __shared__ int loc[E];
    if (threadIdx.x < E) loc[threadIdx.x] = 0;
    __syncthreads();
    const int wid = threadIdx.x >> 5, lane = threadIdx.x & 31;
    const int t = blockIdx.x * 8 + wid;
    const float* xr = x + (size_t)t * C;
    float acc[8] = {0.f, 0.f, 0.f, 0.f, 0.f, 0.f, 0.f, 0.f};
    for (int c = lane; c < C; c += 32) {
        const float xv = xr[c];
        const float4* w4 = reinterpret_cast<const float4*>(wr + (size_t)c * E);
        const float4 a = w4[0], b = w4[1];
        acc[0] += xv * a.x; acc[1] += xv * a.y; acc[2] += xv * a.z; acc[3] += xv * a.w;
        acc[4] += xv * b.x; acc[5] += xv * b.y; acc[6] += xv * b.z; acc[7] += xv * b.w;
    }
    #pragma unroll
    for (int j = 0; j < 8; j++)
        #pragma unroll
        for (int o = 16; o; o >>= 1)
            acc[j] += __shfl_xor_sync(0xFFFFFFFFu, acc[j], o);
    if (lane == 0) {
        float best = -1e30f; int bi = 0;
        #pragma unroll
        for (int j = 0; j < 8; j++) {
            const float v = acc[j] + br[j];
            if (v > best) { best = v; bi = j; }   // first-max, matches argmax
        }
        g_top1[t] = bi;
        atomicAdd(&loc[bi], 1);
    }
    __syncthreads();
    if (threadIdx.x < E) atomicAdd(&g_counts[threadIdx.x], loc[threadIdx.x]);
}

__global__ void k_scan() {
    if (threadIdx.x == 0) {
        int s = 0;
        for (int e = 0; e < E; e++) {
            g_offsets[e] = s;
            g_cursors[e] = s;
            s += g_counts[e];
        }
    }
}

// Fused map + gather: block per token; claim slot, copy fp32 row -> fp16.
__global__ void k_mapgather(const float* __restrict__ x) {
    const int t = blockIdx.x;
    __shared__ int rs;
    if (threadIdx.x == 0) {
        const int e = g_top1[t];
        const int pos = atomicAdd(&g_cursors[e], 1);
        g_tokof[pos] = t;
        rs = pos;
    }
    __syncthreads();
    const int r = rs;
    const float4 v = reinterpret_cast<const float4*>(x + (size_t)t * C)[threadIdx.x];
    __half2* dst = reinterpret_cast<__half2*>(g_Xg + (size_t)r * C) + threadIdx.x * 2;
    dst[0] = __floats2half2_rn(v.x, v.y);
    dst[1] = __floats2half2_rn(v.z, v.w);
}

// ============================================================================
// Stage 2: grouped GEMM via mma.sync (HMMA, fp16 in / fp32 accum)
//   PHASE1: Hg = gelu(Xg @ W1t[e] + b1[e])    (M=cnt, N=4096, K=1024)
//   PHASE2: out[tok] = Hg @ W2t[e] + b2[e]    (M=cnt, N=1024, K=4096)
// A: [M][K] rows, B: [N][K] rows (fp16), mma row.col via ldmatrix.
// BM=256, BN=128, BK=64. 512 threads, 16 warps (4x4 grid, 64x32 warp tile),
// 3-stage cp.async, one __syncthreads per K-chunk, 1 CTA(16 warps)/SM.
// ============================================================================
static constexpr int BM = 256, BN = 128, BK = 64;
static constexpr int A_TILE_B = BM * BK * 2;              // 32 KB
static constexpr int B_TILE_B = BN * BK * 2;              // 16 KB
static constexpr int STAGE_B  = A_TILE_B + B_TILE_B;      // 48 KB
static constexpr int NSTAGE   = 3;
static constexpr int GEMM_SMEM = NSTAGE * STAGE_B;        // 144 KB

template<bool PHASE1>
__global__ void __launch_bounds__(512, 1)
moe_gemm(const float* __restrict__ bias, float* __restrict__ out) {
    constexpr int KT = PHASE1 ? C : H;
    constexpr int NT = PHASE1 ? H : C;
    constexpr int NK = KT / BK;

    extern __shared__ __align__(1024) char smem[];

    const int e   = blockIdx.z;
    const int cnt = g_counts[e];
    const int m0  = blockIdx.y * BM;
    if (m0 >= cnt) return;

    const int tid  = threadIdx.x;
    const int wid  = tid >> 5, lane = tid & 31;
    const int wm   = wid >> 2, wn = wid & 3;      // 4 x 4 warp grid (64x32)
    const int base = g_offsets[e];
    const int valid = min(BM, cnt - m0);
    const int n0   = blockIdx.x * BN;

    const __half* Ag = (PHASE1 ? g_Xg : g_Hg) + (size_t)(base + m0) * KT;
    const __half* Bg = (PHASE1 ? g_w1t : g_w2t) + ((size_t)e * NT + n0) * KT;
    const uint32_t sb = smem_u32(smem);

    // global->shared: thread -> rows gr+64h, 16B chunk gc (8 chunks/row)
    const int gr = tid >> 3, gc = tid & 7;

    auto issue = [&](int kc) {
        const uint32_t As = sb + (uint32_t)(kc % NSTAGE) * STAGE_B;
        const uint32_t Bs = As + A_TILE_B;
        #pragma unroll
        for (int h = 0; h < 4; h++) {             // A rows: gr, +64, +128, +192
            const int row = gr + h * 64;
            const int rA = (row < valid) ? row : 0;
            cp16(As + swz(row, gc), Ag + (size_t)rA * KT + kc * BK + gc * 8,
                 (row < valid) ? 16 : 0);
        }
        #pragma unroll
        for (int h = 0; h < 2; h++) {             // B rows: gr, gr+64
            const int row = gr + h * 64;
            cp16(Bs + swz(row, gc), Bg + (size_t)row * KT + kc * BK + gc * 8, 16);
        }
        CP_COMMIT();
    };

    float acc[4][4][4];
    #pragma unroll
    for (int i = 0; i < 4; i++)
        #pragma unroll
        for (int j = 0; j < 4; j++)
            #pragma unroll
            for (int k = 0; k < 4; k++) acc[i][j][k] = 0.f;

    issue(0);
    issue(1);
    for (int kc = 0; kc < NK; kc++) {
        if (kc + 1 < NK) { CP_WAIT(1); } else { CP_WAIT(0); }
        __syncthreads();
        if (kc + 2 < NK) issue(kc + 2);

        const uint32_t As = sb + (uint32_t)(kc % NSTAGE) * STAGE_B;
        const uint32_t Bs = As + A_TILE_B;
        #pragma unroll
        for (int s = 0; s < 4; s++) {             // 4 x k16 phases per chunk
            uint32_t a[4][4], b[2][4];
            const int ch = s * 2 + (lane >> 4);
            #pragma unroll
            for (int i = 0; i < 4; i++) {
                const int row = wm * 64 + i * 16 + (lane & 15);
                ldsm4(a[i], As + swz(row, ch));
            }
            #pragma unroll
            for (int jj = 0; jj < 2; jj++) {
                const int row = wn * 32 + jj * 16 + (lane & 15);
                ldsm4(b[jj], Bs + swz(row, ch));
            }
            #pragma unroll
            for (int i = 0; i < 4; i++)
                #pragma unroll
                for (int j = 0; j < 4; j++) {
                    const int jj = j >> 1, hh = j & 1;
                    mma16816(acc[i][j], a[i], b[jj][hh], b[jj][hh + 2]);
                }
        }
    }

    // Epilogue: thread holds rows {g, g+8} of each 16-row frag, cols 2q,2q+1
    const int g = lane >> 2, q = lane & 3;
    const float* bp = bias + (size_t)e * NT;
    #pragma unroll
    for (int i = 0; i < 4; i++) {
        #pragma unroll
        for (int hr = 0; hr < 2; hr++) {
            const int row = wm * 64 + i * 16 + g + hr * 8;
            if (row >= valid) continue;
            #pragma unroll
            for (int j = 0; j < 4; j++) {
                const int col = n0 + wn * 32 + j * 8 + q * 2;
                float v0 = acc[i][j][hr * 2 + 0] + bp[col];
                float v1 = acc[i][j][hr * 2 + 1] + bp[col + 1];
                if (PHASE1) {
                    v0 = 0.5f * v0 * (1.0f + erff(v0 * 0.70710678118654752f));
                    v1 = 0.5f * v1 * (1.0f + erff(v1 * 0.70710678118654752f));
                    *reinterpret_cast<__half2*>(
                        g_Hg + (size_t)(base + m0 + row) * H + col) =
                        __floats2half2_rn(v0, v1);
                } else {
                    const int tok = g_tokof[base + m0 + row];
                    float2 v; v.x = v0; v.y = v1;
                    *reinterpret_cast<float2*>(
                        out + (size_t)tok * C + col) = v;
                }
            }
        }
    }
}

// ============================================================================
// kernel_launch
// ============================================================================
extern "C" void kernel_launch(void* const* d_in, const int* in_sizes, int n_in,
                              void* d_out, int out_size) {
    const float* x  = (const float*)d_in[0];
    const float* wr = (const float*)d_in[1];
    const float* br = (const float*)d_in[2];
    const float* w1 = (const float*)d_in[3];
    const float* b1 = (const float*)d_in[4];
    const float* w2 = (const float*)d_in[5];
    const float* b2 = (const float*)d_in[6];
    float* out = (float*)d_out;

    cudaFuncSetAttribute(moe_gemm<true>,
                         cudaFuncAttributeMaxDynamicSharedMemorySize, GEMM_SMEM);
    cudaFuncSetAttribute(moe_gemm<false>,
                         cudaFuncAttributeMaxDynamicSharedMemorySize, GEMM_SMEM);

    k_transpose<0><<<dim3(H / 32, C / 32, E), dim3(32, 8)>>>(w1);   // +zero
    k_transpose<1><<<dim3(C / 32, H / 32, E), dim3(32, 8)>>>(w2);
    k_router<<<NTOK / 8, 256>>>(x, wr, br);                          // +count
    k_scan<<<1, 1>>>();
    k_mapgather<<<NTOK, 256>>>(x);
    moe_gemm<true><<<dim3(H / BN, NTOK / BM, E), 512, GEMM_SMEM>>>(b1, nullptr);
    moe_gemm<false><<<dim3(C / BN, NTOK / BM, E), 512, GEMM_SMEM>>>(b2, out);
}

// round 9
// speedup vs baseline: 1.1785x; 1.1785x over previous
#include <cuda_runtime.h>
#include <cuda_fp16.h>
#include <cstdint>

// ============================================================================
// Problem dims (fixed): x [4,2048,1024], E=8 experts, H=4096
// ============================================================================
static constexpr int NTOK = 8192;   // B*T
static constexpr int C    = 1024;
static constexpr int H    = 4096;
static constexpr int E    = 8;

// ============================================================================
// Scratch (static __device__ — no allocation allowed)
// ============================================================================
__device__ __half g_w1c[(size_t)E * C * H];   // fp16 copy of w1, [E][C][H] (K-major)
__device__ __half g_w2c[(size_t)E * H * C];   // fp16 copy of w2, [E][H][C] (K-major)
__device__ __half g_Xg [(size_t)NTOK * C];    // gathered tokens, fp16
__device__ __half g_Hg [(size_t)NTOK * H];    // hidden activations, fp16
__device__ int    g_top1[NTOK];
__device__ int    g_tokof[NTOK];
__device__ int    g_counts[E];
__device__ int    g_offsets[E];
__device__ int    g_cursors[E];

#define DI __device__ __forceinline__

DI uint32_t smem_u32(const void* p) {
    uint32_t r;
    asm("{ .reg .u64 t; cvta.to.shared.u64 t, %1; cvt.u32.u64 %0, t; }"
        : "=r"(r) : "l"(p));
    return r;
}

// 16B async copy, zero-fill when srcsize==0
DI void cp16(uint32_t dst, const void* src, int srcsize) {
    asm volatile("cp.async.cg.shared.global [%0], [%1], 16, %2;"
                 :: "r"(dst), "l"(src), "r"(srcsize) : "memory");
}
#define CP_COMMIT() asm volatile("cp.async.commit_group;" ::: "memory")
#define CP_WAIT(n)  asm volatile("cp.async.wait_group %0;" :: "n"(n) : "memory")

DI void ldsm4(uint32_t* r, uint32_t addr) {
    asm volatile("ldmatrix.sync.aligned.m8n8.x4.shared.b16 {%0,%1,%2,%3}, [%4];"
                 : "=r"(r[0]), "=r"(r[1]), "=r"(r[2]), "=r"(r[3]) : "r"(addr));
}

DI void ldsm4t(uint32_t* r, uint32_t addr) {
    asm volatile("ldmatrix.sync.aligned.m8n8.x4.trans.shared.b16 {%0,%1,%2,%3}, [%4];"
                 : "=r"(r[0]), "=r"(r[1]), "=r"(r[2]), "=r"(r[3]) : "r"(addr));
}

DI void mma16816(float* d, const uint32_t* a, uint32_t b0, uint32_t b1) {
    asm volatile(
        "mma.sync.aligned.m16n8k16.row.col.f32.f16.f16.f32 "
        "{%0,%1,%2,%3}, {%4,%5,%6,%7}, {%8,%9}, {%0,%1,%2,%3};"
        : "+f"(d[0]), "+f"(d[1]), "+f"(d[2]), "+f"(d[3])
        : "r"(a[0]), "r"(a[1]), "r"(a[2]), "r"(a[3]), "r"(b0), "r"(b1));
}

// A tile: 128B rows (64 halves), 8x16B chunks, chunk ^= row&7.
DI uint32_t swzA(int row, int chunk) {
    return (uint32_t)(row * 128 + ((chunk ^ (row & 7)) << 4));
}
// B tile: 256B rows (128 halves), 16x16B chunks, chunk ^= row&7 (low 3 bits).
DI uint32_t swzB(int row, int chunk) {
    return (uint32_t)(row * 256 + ((chunk ^ (row & 7)) << 4));
}

// ============================================================================
// Stage 1: setup kernels
// ============================================================================

// Streaming fp32 -> fp16 convert (no transpose; layout preserved).
// ZERO==1 also zeroes the expert counters.
template<int ZERO>
__global__ void k_convert(const float* __restrict__ in, __half* __restrict__ outp,
                          int n4) {
    if (ZERO && blockIdx.x == 0 && threadIdx.x < E) g_counts[threadIdx.x] = 0;
    const int stride = gridDim.x * blockDim.x;
    for (int i = blockIdx.x * blockDim.x + threadIdx.x; i < n4; i += stride) {
        const float4 v = reinterpret_cast<const float4*>(in)[i];
        __half2 h0 = __floats2half2_rn(v.x, v.y);
        __half2 h1 = __floats2half2_rn(v.z, v.w);
        uint2 pk;
        pk.x = *reinterpret_cast<uint32_t*>(&h0);
        pk.y = *reinterpret_cast<uint32_t*>(&h1);
        reinterpret_cast<uint2*>(outp)[i] = pk;
    }
}

// Router + histogram: one warp per token. argmax(logits)==argmax(softmax).
__global__ void k_router(const float* __restrict__ x,
                         const float* __restrict__ wr,
                         const float* __restrict__ br) {
    __shared__ int loc[E];
    if (threadIdx.x < E) loc[threadIdx.x] = 0;
    __syncthreads();
    const int wid = threadIdx.x >> 5, lane = threadIdx.x & 31;
    const int t = blockIdx.x * 8 + wid;
    const float* xr = x + (size_t)t * C;
    float acc[8] = {0.f, 0.f, 0.f, 0.f, 0.f, 0.f, 0.f, 0.f};
    for (int c = lane; c < C; c += 32) {
        const float xv = xr[c];
        const float4* w4 = reinterpret_cast<const float4*>(wr + (size_t)c * E);
        const float4 a = w4[0], b = w4[1];
        acc[0] += xv * a.x; acc[1] += xv * a.y; acc[2] += xv * a.z; acc[3] += xv * a.w;
        acc[4] += xv * b.x; acc[5] += xv * b.y; acc[6] += xv * b.z; acc[7] += xv * b.w;
    }
    #pragma unroll
    for (int j = 0; j < 8; j++)
        #pragma unroll
        for (int o = 16; o; o >>= 1)
            acc[j] += __shfl_xor_sync(0xFFFFFFFFu, acc[j], o);
    if (lane == 0) {
        float best = -1e30f; int bi = 0;
        #pragma unroll
        for (int j = 0; j < 8; j++) {
            const float v = acc[j] + br[j];
            if (v > best) { best = v; bi = j; }   // first-max, matches argmax
        }
        g_top1[t] = bi;
        atomicAdd(&loc[bi], 1);
    }
    __syncthreads();
    if (threadIdx.x < E) atomicAdd(&g_counts[threadIdx.x], loc[threadIdx.x]);
}

__global__ void k_scan() {
    if (threadIdx.x == 0) {
        int s = 0;
        for (int e = 0; e < E; e++) {
            g_offsets[e] = s;
            g_cursors[e] = s;
            s += g_counts[e];
        }
    }
}

// Fused map + gather: block per token; claim slot, copy fp32 row -> fp16.
__global__ void k_mapgather(const float* __restrict__ x) {
    const int t = blockIdx.x;
    __shared__ int rs;
    if (threadIdx.x == 0) {
        const int e = g_top1[t];
        const int pos = atomicAdd(&g_cursors[e], 1);
        g_tokof[pos] = t;
        rs = pos;
    }
    __syncthreads();
    const int r = rs;
    const float4 v = reinterpret_cast<const float4*>(x + (size_t)t * C)[threadIdx.x];
    __half2* dst = reinterpret_cast<__half2*>(g_Xg + (size_t)r * C) + threadIdx.x * 2;
    dst[0] = __floats2half2_rn(v.x, v.y);
    dst[1] = __floats2half2_rn(v.z, v.w);
}

// ============================================================================
// Stage 2: grouped GEMM via mma.sync (HMMA, fp16 in / fp32 accum)
//   PHASE1: Hg = gelu(Xg @ w1[e] + b1[e])    (M=cnt, N=4096, K=1024)
//   PHASE2: out[tok] = Hg @ w2[e] + b2[e]    (M=cnt, N=1024, K=4096)
// A: [M][K] rows (ldmatrix), B: [K][N] K-major rows (ldmatrix.trans).
// BM=BN=128, BK=64, 8 warps (2x4, 64x32 warp tile), 3-stage cp.async,
// one __syncthreads per K-chunk, 2 CTAs/SM.
// ============================================================================
static constexpr int BM = 128, BN = 128, BK = 64;
static constexpr int A_TILE_B = BM * BK * 2;              // 16 KB
static constexpr int B_TILE_B = BK * BN * 2;              // 16 KB
static constexpr int STAGE_B  = A_TILE_B + B_TILE_B;      // 32 KB
static constexpr int NSTAGE   = 3;
static constexpr int GEMM_SMEM = NSTAGE * STAGE_B;        // 96 KB

template<bool PHASE1>
__global__ void __launch_bounds__(256, 2)
moe_gemm(const float* __restrict__ bias, float* __restrict__ out) {
    constexpr int KT = PHASE1 ? C : H;
    constexpr int NT = PHASE1 ? H : C;
    constexpr int NK = KT / BK;

    extern __shared__ __align__(1024) char smem[];

    const int e   = blockIdx.z;
    const int cnt = g_counts[e];
    const int m0  = blockIdx.y * BM;
    if (m0 >= cnt) return;

    const int tid  = threadIdx.x;
    const int wid  = tid >> 5, lane = tid & 31;
    const int wm   = wid >> 2, wn = wid & 3;      // 2 x 4 warp grid (64x32)
    const int base = g_offsets[e];
    const int valid = min(BM, cnt - m0);
    const int n0   = blockIdx.x * BN;

    const __half* Ag = (PHASE1 ? g_Xg : g_Hg) + (size_t)(base + m0) * KT;
    const __half* Bg = (PHASE1 ? g_w1c : g_w2c) + (size_t)e * KT * NT + n0;
    const uint32_t sb = smem_u32(smem);

    // A loader: rows gr+32h (h=0..3), 16B chunk gc of 8 per 128B row
    const int gr = tid >> 3, gc = tid & 7;
    // B loader: rows rb+32h (h=0..1), chunks 2*cb, 2*cb+1 of 16 per 256B row
    const int rb = tid >> 3, cb = tid & 7;

    auto issue = [&](int kc) {
        const uint32_t As = sb + (uint32_t)(kc % NSTAGE) * STAGE_B;
        const uint32_t Bs = As + A_TILE_B;
        #pragma unroll
        for (int h = 0; h < 4; h++) {
            const int row = gr + h * 32;
            const int rA = (row < valid) ? row : 0;
            cp16(As + swzA(row, gc), Ag + (size_t)rA * KT + kc * BK + gc * 8,
                 (row < valid) ? 16 : 0);
        }
        #pragma unroll
        for (int h = 0; h < 2; h++) {             // B: 64 K-rows x 256B
            const int krow = rb + h * 32;
            const __half* src = Bg + (size_t)(kc * BK + krow) * NT;
            #pragma unroll
            for (int cc = 0; cc < 2; cc++) {
                const int chunk = cb * 2 + cc;
                cp16(Bs + swzB(krow, chunk), src + chunk * 8, 16);
            }
        }
        CP_COMMIT();
    };

    float acc[4][4][4];
    #pragma unroll
    for (int i = 0; i < 4; i++)
        #pragma unroll
        for (int j = 0; j < 4; j++)
            #pragma unroll
            for (int k = 0; k < 4; k++) acc[i][j][k] = 0.f;

    issue(0);
    issue(1);
    for (int kc = 0; kc < NK; kc++) {
        if (kc + 1 < NK) { CP_WAIT(1); } else { CP_WAIT(0); }
        __syncthreads();
        if (kc + 2 < NK) issue(kc + 2);

        const uint32_t As = sb + (uint32_t)(kc % NSTAGE) * STAGE_B;
        const uint32_t Bs = As + A_TILE_B;
        #pragma unroll
        for (int s = 0; s < 4; s++) {             // 4 x k16 phases per chunk
            uint32_t a[4][4], b[2][4];
            const int ch = s * 2 + (lane >> 4);
            #pragma unroll
            for (int i = 0; i < 4; i++) {
                const int row = wm * 64 + i * 16 + (lane & 15);
                ldsm4(a[i], As + swzA(row, ch));
            }
            // B fragments via ldmatrix.trans on K-major tile:
            // addr rows = k-phase rows (lane%16), cols advance by 8 for lane>=16
            #pragma unroll
            for (int jj = 0; jj < 2; jj++) {
                const int krow = s * 16 + (lane & 15);
                const int ncol = wn * 32 + jj * 16 + (lane >> 4) * 8;
                ldsm4t(b[jj], Bs + swzB(krow, ncol >> 3));
            }
            // b[jj] = {b0,b1 of n8-frag0, b0,b1 of n8-frag1} within n16 jj
            #pragma unroll
            for (int i = 0; i < 4; i++)
                #pragma unroll
                for (int j = 0; j < 4; j++) {
                    const int jj = j >> 1, f = j & 1;
                    mma16816(acc[i][j], a[i], b[jj][f * 2], b[jj][f * 2 + 1]);
                }
        }
    }

    // Epilogue: thread holds rows {g, g+8} of each 16-row frag, cols 2q,2q+1
    const int g = lane >> 2, q = lane & 3;
    const float* bp = bias + (size_t)e * NT;
    #pragma unroll
    for (int i = 0; i < 4; i++) {
        #pragma unroll
        for (int hr = 0; hr < 2; hr++) {
            const int row = wm * 64 + i * 16 + g + hr * 8;
            if (row >= valid) continue;
            #pragma unroll
            for (int j = 0; j < 4; j++) {
                const int col = n0 + wn * 32 + j * 8 + q * 2;
                float v0 = acc[i][j][hr * 2 + 0] + bp[col];
                float v1 = acc[i][j][hr * 2 + 1] + bp[col + 1];
                if (PHASE1) {
                    v0 = 0.5f * v0 * (1.0f + erff(v0 * 0.70710678118654752f));
                    v1 = 0.5f * v1 * (1.0f + erff(v1 * 0.70710678118654752f));
                    *reinterpret_cast<__half2*>(
                        g_Hg + (size_t)(base + m0 + row) * H + col) =
                        __floats2half2_rn(v0, v1);
                } else {
                    const int tok = g_tokof[base + m0 + row];
                    float2 v; v.x = v0; v.y = v1;
                    *reinterpret_cast<float2*>(
                        out + (size_t)tok * C + col) = v;
                }
            }
        }
    }
}

// ============================================================================
// kernel_launch  (GEMM1 is launch #6 -> lands under ncu -s 5 -c 1)
// ============================================================================
extern "C" void kernel_launch(void* const* d_in, const int* in_sizes, int n_in,
                              void* d_out, int out_size) {
    const float* x  = (const float*)d_in[0];
    const float* wr = (const float*)d_in[1];
    const float* br = (const float*)d_in[2];
    const float* w1 = (const float*)d_in[3];
    const float* b1 = (const float*)d_in[4];
    const float* w2 = (const float*)d_in[5];
    const float* b2 = (const float*)d_in[6];
    float* out = (float*)d_out;

    cudaFuncSetAttribute(moe_gemm<true>,
                         cudaFuncAttributeMaxDynamicSharedMemorySize, GEMM_SMEM);
    cudaFuncSetAttribute(moe_gemm<false>,
                         cudaFuncAttributeMaxDynamicSharedMemorySize, GEMM_SMEM);

    constexpr int N4 = (E * C * H) / 4;          // 8.39M float4s per weight tensor
    __half* w1c; cudaGetSymbolAddress((void**)&w1c, g_w1c);
    __half* w2c; cudaGetSymbolAddress((void**)&w2c, g_w2c);

    k_convert<1><<<4096, 256>>>(w1, w1c, N4);    // #1 (+zero counters)
    k_convert<0><<<4096, 256>>>(w2, w2c, N4);    // #2
    k_router<<<NTOK / 8, 256>>>(x, wr, br);      // #3 (+count)
    k_scan<<<1, 1>>>();                          // #4
    k_mapgather<<<NTOK, 256>>>(x);               // #5
    moe_gemm<true><<<dim3(H / BN, NTOK / BM, E), 256, GEMM_SMEM>>>(b1, nullptr);  // #6
    moe_gemm<false><<<dim3(C / BN, NTOK / BM, E), 256, GEMM_SMEM>>>(b2, out);     // #7
}

// round 10
// speedup vs baseline: 1.1840x; 1.0047x over previous
#include <cuda_runtime.h>
#include <cuda_fp16.h>
#include <cstdint>

// ============================================================================
// Problem dims (fixed): x [4,2048,1024], E=8 experts, H=4096
// ============================================================================
static constexpr int NTOK = 8192;   // B*T
static constexpr int C    = 1024;
static constexpr int H    = 4096;
static constexpr int E    = 8;

// ============================================================================
// Scratch (static __device__ — no allocation allowed)
// ============================================================================
__device__ __half g_w1c[(size_t)E * C * H];   // fp16 copy of w1, [E][C][H] (K-major)
__device__ __half g_w2c[(size_t)E * H * C];   // fp16 copy of w2, [E][H][C] (K-major)
__device__ __half g_Xg [(size_t)NTOK * C];    // gathered tokens, fp16
__device__ __half g_Hg [(size_t)NTOK * H];    // hidden activations, fp16
__device__ int    g_top1[NTOK];
__device__ int    g_tokof[NTOK];
__device__ int    g_counts[E];
__device__ int    g_offsets[E];
__device__ int    g_cursors[E];
__device__ int    g_done;

#define DI __device__ __forceinline__

DI uint32_t smem_u32(const void* p) {
    uint32_t r;
    asm("{ .reg .u64 t; cvta.to.shared.u64 t, %1; cvt.u32.u64 %0, t; }"
        : "=r"(r) : "l"(p));
    return r;
}

// 16B async copy, zero-fill when srcsize==0
DI void cp16(uint32_t dst, const void* src, int srcsize) {
    asm volatile("cp.async.cg.shared.global [%0], [%1], 16, %2;"
                 :: "r"(dst), "l"(src), "r"(srcsize) : "memory");
}
#define CP_COMMIT() asm volatile("cp.async.commit_group;" ::: "memory")
#define CP_WAIT(n)  asm volatile("cp.async.wait_group %0;" :: "n"(n) : "memory")

DI void ldsm4(uint32_t* r, uint32_t addr) {
    asm volatile("ldmatrix.sync.aligned.m8n8.x4.shared.b16 {%0,%1,%2,%3}, [%4];"
                 : "=r"(r[0]), "=r"(r[1]), "=r"(r[2]), "=r"(r[3]) : "r"(addr));
}

DI void ldsm4t(uint32_t* r, uint32_t addr) {
    asm volatile("ldmatrix.sync.aligned.m8n8.x4.trans.shared.b16 {%0,%1,%2,%3}, [%4];"
                 : "=r"(r[0]), "=r"(r[1]), "=r"(r[2]), "=r"(r[3]) : "r"(addr));
}

DI void mma16816(float* d, const uint32_t* a, uint32_t b0, uint32_t b1) {
    asm volatile(
        "mma.sync.aligned.m16n8k16.row.col.f32.f16.f16.f32 "
        "{%0,%1,%2,%3}, {%4,%5,%6,%7}, {%8,%9}, {%0,%1,%2,%3};"
        : "+f"(d[0]), "+f"(d[1]), "+f"(d[2]), "+f"(d[3])
        : "r"(a[0]), "r"(a[1]), "r"(a[2]), "r"(a[3]), "r"(b0), "r"(b1));
}

// A tile: 128B rows (64 halves), 8x16B chunks, chunk ^= row&7.
DI uint32_t swzA(int row, int chunk) {
    return (uint32_t)(row * 128 + ((chunk ^ (row & 7)) << 4));
}
// B tile: 256B rows (128 halves), 16x16B chunks, chunk ^= row&7 (low 3 bits).
DI uint32_t swzB(int row, int chunk) {
    return (uint32_t)(row * 256 + ((chunk ^ (row & 7)) << 4));
}

// ============================================================================
// Stage 1: setup kernels
// ============================================================================

// Streaming fp32 -> fp16 convert of BOTH weight tensors (layout preserved).
// Also zeroes the router counters.
__global__ void k_convert(const float* __restrict__ w1, const float* __restrict__ w2,
                          __half* __restrict__ w1c, __half* __restrict__ w2c,
                          int n4) {
    if (blockIdx.x == 0 && threadIdx.x <= E) {
        if (threadIdx.x < E) g_counts[threadIdx.x] = 0;
        else                 g_done = 0;
    }
    const int stride = gridDim.x * blockDim.x;
    for (int i = blockIdx.x * blockDim.x + threadIdx.x; i < 2 * n4; i += stride) {
        const bool second = (i >= n4);
        const int idx = second ? i - n4 : i;
        const float4 v = reinterpret_cast<const float4*>(second ? w2 : w1)[idx];
        __half2 h0 = __floats2half2_rn(v.x, v.y);
        __half2 h1 = __floats2half2_rn(v.z, v.w);
        uint2 pk;
        pk.x = *reinterpret_cast<uint32_t*>(&h0);
        pk.y = *reinterpret_cast<uint32_t*>(&h1);
        reinterpret_cast<uint2*>(second ? w2c : w1c)[idx] = pk;
    }
}

// Router + histogram + (last block) offset scan.
// One warp per token. argmax(logits)==argmax(softmax).
__global__ void k_router(const float* __restrict__ x,
                         const float* __restrict__ wr,
                         const float* __restrict__ br) {
    __shared__ int loc[E];
    if (threadIdx.x < E) loc[threadIdx.x] = 0;
    __syncthreads();
    const int wid = threadIdx.x >> 5, lane = threadIdx.x & 31;
    const int t = blockIdx.x * 8 + wid;
    const float* xr = x + (size_t)t * C;
    float acc[8] = {0.f, 0.f, 0.f, 0.f, 0.f, 0.f, 0.f, 0.f};
    for (int c = lane; c < C; c += 32) {
        const float xv = xr[c];
        const float4* w4 = reinterpret_cast<const float4*>(wr + (size_t)c * E);
        const float4 a = w4[0], b = w4[1];
        acc[0] += xv * a.x; acc[1] += xv * a.y; acc[2] += xv * a.z; acc[3] += xv * a.w;
        acc[4] += xv * b.x; acc[5] += xv * b.y; acc[6] += xv * b.z; acc[7] += xv * b.w;
    }
    #pragma unroll
    for (int j = 0; j < 8; j++)
        #pragma unroll
        for (int o = 16; o; o >>= 1)
            acc[j] += __shfl_xor_sync(0xFFFFFFFFu, acc[j], o);
    if (lane == 0) {
        float best = -1e30f; int bi = 0;
        #pragma unroll
        for (int j = 0; j < 8; j++) {
            const float v = acc[j] + br[j];
            if (v > best) { best = v; bi = j; }   // first-max, matches argmax
        }
        g_top1[t] = bi;
        atomicAdd(&loc[bi], 1);
    }
    __syncthreads();
    if (threadIdx.x < E) atomicAdd(&g_counts[threadIdx.x], loc[threadIdx.x]);
    // last block computes exclusive scan -> offsets & cursors
    __threadfence();
    __syncthreads();
    if (threadIdx.x == 0) {
        if (atomicAdd(&g_done, 1) == (int)gridDim.x - 1) {
            int s = 0;
            for (int e = 0; e < E; e++) {
                g_offsets[e] = s;
                g_cursors[e] = s;
                s += g_counts[e];
            }
            __threadfence();
        }
    }
}

// Fused map + gather: block per token; claim slot, copy fp32 row -> fp16.
__global__ void k_mapgather(const float* __restrict__ x) {
    const int t = blockIdx.x;
    __shared__ int rs;
    if (threadIdx.x == 0) {
        const int e = g_top1[t];
        const int pos = atomicAdd(&g_cursors[e], 1);
        g_tokof[pos] = t;
        rs = pos;
    }
    __syncthreads();
    const int r = rs;
    const float4 v = reinterpret_cast<const float4*>(x + (size_t)t * C)[threadIdx.x];
    __half2* dst = reinterpret_cast<__half2*>(g_Xg + (size_t)r * C) + threadIdx.x * 2;
    dst[0] = __floats2half2_rn(v.x, v.y);
    dst[1] = __floats2half2_rn(v.z, v.w);
}

// ============================================================================
// Stage 2: grouped GEMM via mma.sync (HMMA, fp16 in / fp32 accum)
//   PHASE1: Hg = gelu(Xg @ w1[e] + b1[e])    (M=cnt, N=4096, K=1024)
//   PHASE2: out[tok] = Hg @ w2[e] + b2[e]    (M=cnt, N=1024, K=4096)
// A: [M][K] rows (ldmatrix), B: [K][N] K-major rows (ldmatrix.trans).
// BM=BN=128, BK=64, 8 warps (2x4, 64x32 warp tile), 3-stage cp.async,
// one __syncthreads per K-chunk, 2 CTAs/SM. Grouped raster (GROUP_M=8).
// ============================================================================
static constexpr int BM = 128, BN = 128, BK = 64;
static constexpr int A_TILE_B = BM * BK * 2;              // 16 KB
static constexpr int B_TILE_B = BK * BN * 2;              // 16 KB
static constexpr int STAGE_B  = A_TILE_B + B_TILE_B;      // 32 KB
static constexpr int NSTAGE   = 3;
static constexpr int GEMM_SMEM = NSTAGE * STAGE_B;        // 96 KB
static constexpr int GROUP_M  = 8;

template<bool PHASE1>
__global__ void __launch_bounds__(256, 2)
moe_gemm(const float* __restrict__ bias, float* __restrict__ out) {
    constexpr int KT = PHASE1 ? C : H;
    constexpr int NT = PHASE1 ? H : C;
    constexpr int NK = KT / BK;
    constexpr int TILES_N = NT / BN;

    extern __shared__ __align__(1024) char smem[];

    // Grouped raster: wave covers GROUP_M m-tiles x all n-tiles of one expert.
    const int e   = blockIdx.z;
    const int cnt = g_counts[e];
    const int pid = blockIdx.y * TILES_N + blockIdx.x;
    const int gsz = GROUP_M * TILES_N;
    const int m_tile = (pid / gsz) * GROUP_M + (pid % GROUP_M);
    const int n_tile = (pid % gsz) / GROUP_M;
    const int m0  = m_tile * BM;
    if (m0 >= cnt) return;

    const int tid  = threadIdx.x;
    const int wid  = tid >> 5, lane = tid & 31;
    const int wm   = wid >> 2, wn = wid & 3;      // 2 x 4 warp grid (64x32)
    const int base = g_offsets[e];
    const int valid = min(BM, cnt - m0);
    const int n0   = n_tile * BN;

    const __half* Ag = (PHASE1 ? g_Xg : g_Hg) + (size_t)(base + m0) * KT;
    const __half* Bg = (PHASE1 ? g_w1c : g_w2c) + (size_t)e * KT * NT + n0;
    const uint32_t sb = smem_u32(smem);

    // A loader: rows gr+32h (h=0..3), 16B chunk gc of 8 per 128B row
    const int gr = tid >> 3, gc = tid & 7;
    // B loader: rows rb+32h (h=0..1), chunks 2*cb, 2*cb+1 of 16 per 256B row
    const int rb = tid >> 3, cb = tid & 7;

    auto issue = [&](int kc) {
        const uint32_t As = sb + (uint32_t)(kc % NSTAGE) * STAGE_B;
        const uint32_t Bs = As + A_TILE_B;
        #pragma unroll
        for (int h = 0; h < 4; h++) {
            const int row = gr + h * 32;
            const int rA = (row < valid) ? row : 0;
            cp16(As + swzA(row, gc), Ag + (size_t)rA * KT + kc * BK + gc * 8,
                 (row < valid) ? 16 : 0);
        }
        #pragma unroll
        for (int h = 0; h < 2; h++) {             // B: 64 K-rows x 256B
            const int krow = rb + h * 32;
            const __half* src = Bg + (size_t)(kc * BK + krow) * NT;
            #pragma unroll
            for (int cc = 0; cc < 2; cc++) {
                const int chunk = cb * 2 + cc;
                cp16(Bs + swzB(krow, chunk), src + chunk * 8, 16);
            }
        }
        CP_COMMIT();
    };

    float acc[4][4][4];
    #pragma unroll
    for (int i = 0; i < 4; i++)
        #pragma unroll
        for (int j = 0; j < 4; j++)
            #pragma unroll
            for (int k = 0; k < 4; k++) acc[i][j][k] = 0.f;

    issue(0);
    issue(1);
    for (int kc = 0; kc < NK; kc++) {
        if (kc + 1 < NK) { CP_WAIT(1); } else { CP_WAIT(0); }
        __syncthreads();
        if (kc + 2 < NK) issue(kc + 2);

        const uint32_t As = sb + (uint32_t)(kc % NSTAGE) * STAGE_B;
        const uint32_t Bs = As + A_TILE_B;
        #pragma unroll
        for (int s = 0; s < 4; s++) {             // 4 x k16 phases per chunk
            uint32_t a[4][4], b[2][4];
            const int ch = s * 2 + (lane >> 4);
            #pragma unroll
            for (int i = 0; i < 4; i++) {
                const int row = wm * 64 + i * 16 + (lane & 15);
                ldsm4(a[i], As + swzA(row, ch));
            }
            // B fragments via ldmatrix.trans on K-major tile
            #pragma unroll
            for (int jj = 0; jj < 2; jj++) {
                const int krow = s * 16 + (lane & 15);
                const int ncol = wn * 32 + jj * 16 + (lane >> 4) * 8;
                ldsm4t(b[jj], Bs + swzB(krow, ncol >> 3));
            }
            #pragma unroll
            for (int i = 0; i < 4; i++)
                #pragma unroll
                for (int j = 0; j < 4; j++) {
                    const int jj = j >> 1, f = j & 1;
                    mma16816(acc[i][j], a[i], b[jj][f * 2], b[jj][f * 2 + 1]);
                }
        }
    }

    // Epilogue: thread holds rows {g, g+8} of each 16-row frag, cols 2q,2q+1
    const int g = lane >> 2, q = lane & 3;
    const float* bp = bias + (size_t)e * NT;
    #pragma unroll
    for (int i = 0; i < 4; i++) {
        #pragma unroll
        for (int hr = 0; hr < 2; hr++) {
            const int row = wm * 64 + i * 16 + g + hr * 8;
            if (row >= valid) continue;
            #pragma unroll
            for (int j = 0; j < 4; j++) {
                const int col = n0 + wn * 32 + j * 8 + q * 2;
                float v0 = acc[i][j][hr * 2 + 0] + bp[col];
                float v1 = acc[i][j][hr * 2 + 1] + bp[col + 1];
                if (PHASE1) {
                    v0 = 0.5f * v0 * (1.0f + erff(v0 * 0.70710678118654752f));
                    v1 = 0.5f * v1 * (1.0f + erff(v1 * 0.70710678118654752f));
                    *reinterpret_cast<__half2*>(
                        g_Hg + (size_t)(base + m0 + row) * H + col) =
                        __floats2half2_rn(v0, v1);
                } else {
                    const int tok = g_tokof[base + m0 + row];
                    float2 v; v.x = v0; v.y = v1;
                    *reinterpret_cast<float2*>(
                        out + (size_t)tok * C + col) = v;
                }
            }
        }
    }
}

// ============================================================================
// kernel_launch  (GEMM1 is OUR launch #4 -> lands under ncu skip window)
// ============================================================================
extern "C" void kernel_launch(void* const* d_in, const int* in_sizes, int n_in,
                              void* d_out, int out_size) {
    const float* x  = (const float*)d_in[0];
    const float* wr = (const float*)d_in[1];
    const float* br = (const float*)d_in[2];
    const float* w1 = (const float*)d_in[3];
    const float* b1 = (const float*)d_in[4];
    const float* w2 = (const float*)d_in[5];
    const float* b2 = (const float*)d_in[6];
    float* out = (float*)d_out;

    cudaFuncSetAttribute(moe_gemm<true>,
                         cudaFuncAttributeMaxDynamicSharedMemorySize, GEMM_SMEM);
    cudaFuncSetAttribute(moe_gemm<false>,
                         cudaFuncAttributeMaxDynamicSharedMemorySize, GEMM_SMEM);

    constexpr int N4 = (E * C * H) / 4;          // 8.39M float4s per weight tensor
    __half* w1c; cudaGetSymbolAddress((void**)&w1c, g_w1c);
    __half* w2c; cudaGetSymbolAddress((void**)&w2c, g_w2c);

    k_convert<<<4096, 256>>>(w1, w2, w1c, w2c, N4);   // #1 (+zero counters)
    k_router<<<NTOK / 8, 256>>>(x, wr, br);            // #2 (+count +scan)
    k_mapgather<<<NTOK, 256>>>(x);                     // #3
    moe_gemm<true><<<dim3(H / BN, NTOK / BM, E), 256, GEMM_SMEM>>>(b1, nullptr);  // #4
    moe_gemm<false><<<dim3(C / BN, NTOK / BM, E), 256, GEMM_SMEM>>>(b2, out);     // #5
}

// round 11
// speedup vs baseline: 1.2066x; 1.0190x over previous
#include <cuda_runtime.h>
#include <cuda_fp16.h>
#include <cstdint>

// ============================================================================
// Problem dims (fixed): x [4,2048,1024], E=8 experts, H=4096
// ============================================================================
static constexpr int NTOK = 8192;   // B*T
static constexpr int C    = 1024;
static constexpr int H    = 4096;
static constexpr int E    = 8;

static constexpr int BM = 128, BN = 128, BK = 64;
static constexpr int MAX_TILES = 72;    // sum ceil(cnt_e/BM) <= 64 + 7

// ============================================================================
// Scratch (static __device__ — no allocation allowed)
// ============================================================================
__device__ __half g_w1c[(size_t)E * C * H];   // fp16 copy of w1, [E][C][H] (K-major)
__device__ __half g_w2c[(size_t)E * H * C];   // fp16 copy of w2, [E][H][C] (K-major)
__device__ __half g_Xg [(size_t)NTOK * C];    // gathered tokens, fp16
__device__ __half g_Hg [(size_t)NTOK * H];    // hidden activations, fp16
__device__ int    g_top1[NTOK];
__device__ int    g_tokof[NTOK];
__device__ int    g_counts[E];
__device__ int    g_offsets[E];
__device__ int    g_cursors[E];
__device__ int    g_done;
__device__ int    g_ntiles;
__device__ int    g_tiles[MAX_TILES];          // (e << 16) | m_tile

#define DI __device__ __forceinline__

DI uint32_t smem_u32(const void* p) {
    uint32_t r;
    asm("{ .reg .u64 t; cvta.to.shared.u64 t, %1; cvt.u32.u64 %0, t; }"
        : "=r"(r) : "l"(p));
    return r;
}

// 16B async copy, zero-fill when srcsize==0
DI void cp16(uint32_t dst, const void* src, int srcsize) {
    asm volatile("cp.async.cg.shared.global [%0], [%1], 16, %2;"
                 :: "r"(dst), "l"(src), "r"(srcsize) : "memory");
}
#define CP_COMMIT() asm volatile("cp.async.commit_group;" ::: "memory")
#define CP_WAIT(n)  asm volatile("cp.async.wait_group %0;" :: "n"(n) : "memory")

DI void ldsm4(uint32_t* r, uint32_t addr) {
    asm volatile("ldmatrix.sync.aligned.m8n8.x4.shared.b16 {%0,%1,%2,%3}, [%4];"
                 : "=r"(r[0]), "=r"(r[1]), "=r"(r[2]), "=r"(r[3]) : "r"(addr));
}

DI void ldsm4t(uint32_t* r, uint32_t addr) {
    asm volatile("ldmatrix.sync.aligned.m8n8.x4.trans.shared.b16 {%0,%1,%2,%3}, [%4];"
                 : "=r"(r[0]), "=r"(r[1]), "=r"(r[2]), "=r"(r[3]) : "r"(addr));
}

DI void mma16816(float* d, const uint32_t* a, uint32_t b0, uint32_t b1) {
    asm volatile(
        "mma.sync.aligned.m16n8k16.row.col.f32.f16.f16.f32 "
        "{%0,%1,%2,%3}, {%4,%5,%6,%7}, {%8,%9}, {%0,%1,%2,%3};"
        : "+f"(d[0]), "+f"(d[1]), "+f"(d[2]), "+f"(d[3])
        : "r"(a[0]), "r"(a[1]), "r"(a[2]), "r"(a[3]), "r"(b0), "r"(b1));
}

// A tile: 128B rows (64 halves), 8x16B chunks, chunk ^= row&7.
DI uint32_t swzA(int row, int chunk) {
    return (uint32_t)(row * 128 + ((chunk ^ (row & 7)) << 4));
}
// B tile: 256B rows (128 halves), 16x16B chunks, chunk ^= row&7 (low 3 bits).
DI uint32_t swzB(int row, int chunk) {
    return (uint32_t)(row * 256 + ((chunk ^ (row & 7)) << 4));
}

// ============================================================================
// Stage 1: setup kernels
// ============================================================================

// Streaming fp32 -> fp16 convert of BOTH weight tensors (layout preserved).
__global__ void k_convert(const float* __restrict__ w1, const float* __restrict__ w2,
                          __half* __restrict__ w1c, __half* __restrict__ w2c,
                          int n4) {
    if (blockIdx.x == 0 && threadIdx.x <= E) {
        if (threadIdx.x < E) g_counts[threadIdx.x] = 0;
        else                 g_done = 0;
    }
    const int stride = gridDim.x * blockDim.x;
    for (int i = blockIdx.x * blockDim.x + threadIdx.x; i < 2 * n4; i += stride) {
        const bool second = (i >= n4);
        const int idx = second ? i - n4 : i;
        const float4 v = reinterpret_cast<const float4*>(second ? w2 : w1)[idx];
        __half2 h0 = __floats2half2_rn(v.x, v.y);
        __half2 h1 = __floats2half2_rn(v.z, v.w);
        uint2 pk;
        pk.x = *reinterpret_cast<uint32_t*>(&h0);
        pk.y = *reinterpret_cast<uint32_t*>(&h1);
        reinterpret_cast<uint2*>(second ? w2c : w1c)[idx] = pk;
    }
}

// Router + histogram + (last block) scan + tile table.
__global__ void k_router(const float* __restrict__ x,
                         const float* __restrict__ wr,
                         const float* __restrict__ br) {
    __shared__ int loc[E];
    if (threadIdx.x < E) loc[threadIdx.x] = 0;
    __syncthreads();
    const int wid = threadIdx.x >> 5, lane = threadIdx.x & 31;
    const int t = blockIdx.x * 8 + wid;
    const float* xr = x + (size_t)t * C;
    float acc[8] = {0.f, 0.f, 0.f, 0.f, 0.f, 0.f, 0.f, 0.f};
    for (int c = lane; c < C; c += 32) {
        const float xv = xr[c];
        const float4* w4 = reinterpret_cast<const float4*>(wr + (size_t)c * E);
        const float4 a = w4[0], b = w4[1];
        acc[0] += xv * a.x; acc[1] += xv * a.y; acc[2] += xv * a.z; acc[3] += xv * a.w;
        acc[4] += xv * b.x; acc[5] += xv * b.y; acc[6] += xv * b.z; acc[7] += xv * b.w;
    }
    #pragma unroll
    for (int j = 0; j < 8; j++)
        #pragma unroll
        for (int o = 16; o; o >>= 1)
            acc[j] += __shfl_xor_sync(0xFFFFFFFFu, acc[j], o);
    if (lane == 0) {
        float best = -1e30f; int bi = 0;
        #pragma unroll
        for (int j = 0; j < 8; j++) {
            const float v = acc[j] + br[j];
            if (v > best) { best = v; bi = j; }   // first-max, matches argmax
        }
        g_top1[t] = bi;
        atomicAdd(&loc[bi], 1);
    }
    __syncthreads();
    if (threadIdx.x < E) atomicAdd(&g_counts[threadIdx.x], loc[threadIdx.x]);
    __threadfence();
    __syncthreads();
    if (threadIdx.x == 0) {
        if (atomicAdd(&g_done, 1) == (int)gridDim.x - 1) {
            int s = 0, tt = 0;
            for (int e = 0; e < E; e++) {
                g_offsets[e] = s;
                g_cursors[e] = s;
                const int cnt = g_counts[e];
                for (int mt = 0; mt * BM < cnt; mt++)
                    g_tiles[tt++] = (e << 16) | mt;
                s += cnt;
            }
            g_ntiles = tt;
            __threadfence();
        }
    }
}

// Fused map + gather: block per token; claim slot, copy fp32 row -> fp16.
__global__ void k_mapgather(const float* __restrict__ x) {
    const int t = blockIdx.x;
    __shared__ int rs;
    if (threadIdx.x == 0) {
        const int e = g_top1[t];
        const int pos = atomicAdd(&g_cursors[e], 1);
        g_tokof[pos] = t;
        rs = pos;
    }
    __syncthreads();
    const int r = rs;
    const float4 v = reinterpret_cast<const float4*>(x + (size_t)t * C)[threadIdx.x];
    __half2* dst = reinterpret_cast<__half2*>(g_Xg + (size_t)r * C) + threadIdx.x * 2;
    dst[0] = __floats2half2_rn(v.x, v.y);
    dst[1] = __floats2half2_rn(v.z, v.w);
}

// ============================================================================
// Stage 2: grouped GEMM via mma.sync (HMMA, fp16 in / fp32 accum)
//   PHASE1: Hg = gelu(Xg @ w1[e] + b1[e])    (M=cnt, N=4096, K=1024)
//   PHASE2: out[tok] = Hg @ w2[e] + b2[e]    (M=cnt, N=1024, K=4096)
// A: [M][K] rows (ldmatrix), B: [K][N] K-major rows (ldmatrix.trans).
// BM=BN=128, BK=64, 8 warps (2x4, 64x32 warp tile), 3-stage cp.async,
// register double-buffered fragments, tile-table grid, 2 CTAs/SM.
// ============================================================================
static constexpr int A_TILE_B = BM * BK * 2;              // 16 KB
static constexpr int B_TILE_B = BK * BN * 2;              // 16 KB
static constexpr int STAGE_B  = A_TILE_B + B_TILE_B;      // 32 KB
static constexpr int NSTAGE   = 3;
static constexpr int GEMM_SMEM = NSTAGE * STAGE_B;        // 96 KB

template<bool PHASE1>
__global__ void __launch_bounds__(256, 2)
moe_gemm(const float* __restrict__ bias, float* __restrict__ out) {
    constexpr int KT = PHASE1 ? C : H;
    constexpr int NT = PHASE1 ? H : C;
    constexpr int NK = KT / BK;

    extern __shared__ __align__(1024) char smem[];

    if ((int)blockIdx.y >= g_ntiles) return;
    const int pk  = g_tiles[blockIdx.y];
    const int e   = pk >> 16;
    const int m0  = (pk & 0xFFFF) * BM;
    const int cnt = g_counts[e];

    const int tid  = threadIdx.x;
    const int wid  = tid >> 5, lane = tid & 31;
    const int wm   = wid >> 2, wn = wid & 3;      // 2 x 4 warp grid (64x32)
    const int base = g_offsets[e];
    const int valid = min(BM, cnt - m0);
    const int n0   = blockIdx.x * BN;

    const __half* Ag = (PHASE1 ? g_Xg : g_Hg) + (size_t)(base + m0) * KT;
    const __half* Bg = (PHASE1 ? g_w1c : g_w2c) + (size_t)e * KT * NT + n0;
    const uint32_t sb = smem_u32(smem);

    // loader mapping: rows (tid>>3)+32h, 16B chunks
    const int gr = tid >> 3, gc = tid & 7;

    auto issue = [&](int kc, int st) {
        const uint32_t As = sb + (uint32_t)st * STAGE_B;
        const uint32_t Bs = As + A_TILE_B;
        #pragma unroll
        for (int h = 0; h < 4; h++) {
            const int row = gr + h * 32;
            const int rA = (row < valid) ? row : 0;
            cp16(As + swzA(row, gc), Ag + (size_t)rA * KT + kc * BK + gc * 8,
                 (row < valid) ? 16 : 0);
        }
        #pragma unroll
        for (int h = 0; h < 2; h++) {             // B: 64 K-rows x 256B
            const int krow = gr + h * 32;
            const __half* src = Bg + (size_t)(kc * BK + krow) * NT;
            #pragma unroll
            for (int cc = 0; cc < 2; cc++) {
                const int chunk = gc * 2 + cc;
                cp16(Bs + swzB(krow, chunk), src + chunk * 8, 16);
            }
        }
        CP_COMMIT();
    };

    // compute-side per-thread constants
    const int l15 = lane & 15, hi = lane >> 4;

    auto load_ph = [&](int s, uint32_t (*a)[4], uint32_t (*b)[4],
                       uint32_t As, uint32_t Bs) {
        const int ch = s * 2 + hi;
        #pragma unroll
        for (int i = 0; i < 4; i++) {
            const int row = wm * 64 + i * 16 + l15;
            ldsm4(a[i], As + swzA(row, ch));
        }
        const int krow = s * 16 + l15;
        #pragma unroll
        for (int jj = 0; jj < 2; jj++) {
            const int ncol = wn * 32 + jj * 16 + hi * 8;
            ldsm4t(b[jj], Bs + swzB(krow, ncol >> 3));
        }
    };

    float acc[4][4][4];
    #pragma unroll
    for (int i = 0; i < 4; i++)
        #pragma unroll
        for (int j = 0; j < 4; j++)
            #pragma unroll
            for (int k = 0; k < 4; k++) acc[i][j][k] = 0.f;

    issue(0, 0);
    issue(1, 1);
    int ist = 2, cst = 0;
    for (int kc = 0; kc < NK; kc++) {
        if (kc + 1 < NK) { CP_WAIT(1); } else { CP_WAIT(0); }
        __syncthreads();
        if (kc + 2 < NK) {
            issue(kc + 2, ist);
            ist = (ist + 1 == NSTAGE) ? 0 : ist + 1;
        }

        const uint32_t As = sb + (uint32_t)cst * STAGE_B;
        const uint32_t Bs = As + A_TILE_B;
        cst = (cst + 1 == NSTAGE) ? 0 : cst + 1;

        // register double-buffered fragment pipeline over 4 k16 phases
        uint32_t aP[2][4][4], bP[2][2][4];
        load_ph(0, aP[0], bP[0], As, Bs);
        #pragma unroll
        for (int s = 0; s < 4; s++) {
            if (s < 3) load_ph(s + 1, aP[(s + 1) & 1], bP[(s + 1) & 1], As, Bs);
            uint32_t (*a)[4] = aP[s & 1];
            uint32_t (*b)[4] = bP[s & 1];
            #pragma unroll
            for (int i = 0; i < 4; i++)
                #pragma unroll
                for (int j = 0; j < 4; j++) {
                    const int jj = j >> 1, f = j & 1;
                    mma16816(acc[i][j], a[i], b[jj][f * 2], b[jj][f * 2 + 1]);
                }
        }
    }

    // Epilogue: thread holds rows {g, g+8} of each 16-row frag, cols 2q,2q+1
    const int g = lane >> 2, q = lane & 3;
    const float* bp = bias + (size_t)e * NT;
    #pragma unroll
    for (int i = 0; i < 4; i++) {
        #pragma unroll
        for (int hr = 0; hr < 2; hr++) {
            const int row = wm * 64 + i * 16 + g + hr * 8;
            if (row >= valid) continue;
            #pragma unroll
            for (int j = 0; j < 4; j++) {
                const int col = n0 + wn * 32 + j * 8 + q * 2;
                float v0 = acc[i][j][hr * 2 + 0] + bp[col];
                float v1 = acc[i][j][hr * 2 + 1] + bp[col + 1];
                if (PHASE1) {
                    v0 = 0.5f * v0 * (1.0f + erff(v0 * 0.70710678118654752f));
                    v1 = 0.5f * v1 * (1.0f + erff(v1 * 0.70710678118654752f));
                    *reinterpret_cast<__half2*>(
                        g_Hg + (size_t)(base + m0 + row) * H + col) =
                        __floats2half2_rn(v0, v1);
                } else {
                    const int tok = g_tokof[base + m0 + row];
                    float2 v; v.x = v0; v.y = v1;
                    *reinterpret_cast<float2*>(
                        out + (size_t)tok * C + col) = v;
                }
            }
        }
    }
}

// ============================================================================
// kernel_launch  (GEMM1 is OUR launch #4)
// ============================================================================
extern "C" void kernel_launch(void* const* d_in, const int* in_sizes, int n_in,
                              void* d_out, int out_size) {
    const float* x  = (const float*)d_in[0];
    const float* wr = (const float*)d_in[1];
    const float* br = (const float*)d_in[2];
    const float* w1 = (const float*)d_in[3];
    const float* b1 = (const float*)d_in[4];
    const float* w2 = (const float*)d_in[5];
    const float* b2 = (const float*)d_in[6];
    float* out = (float*)d_out;

    cudaFuncSetAttribute(moe_gemm<true>,
                         cudaFuncAttributeMaxDynamicSharedMemorySize, GEMM_SMEM);
    cudaFuncSetAttribute(moe_gemm<false>,
                         cudaFuncAttributeMaxDynamicSharedMemorySize, GEMM_SMEM);

    constexpr int N4 = (E * C * H) / 4;          // 8.39M float4s per weight tensor
    __half* w1c; cudaGetSymbolAddress((void**)&w1c, g_w1c);
    __half* w2c; cudaGetSymbolAddress((void**)&w2c, g_w2c);

    k_convert<<<4096, 256>>>(w1, w2, w1c, w2c, N4);   // #1 (+zero counters)
    k_router<<<NTOK / 8, 256>>>(x, wr, br);            // #2 (+count +scan +tiles)
    k_mapgather<<<NTOK, 256>>>(x);                     // #3
    moe_gemm<true><<<dim3(H / BN, MAX_TILES), 256, GEMM_SMEM>>>(b1, nullptr);  // #4
    moe_gemm<false><<<dim3(C / BN, MAX_TILES), 256, GEMM_SMEM>>>(b2, out);     // #5
}

// round 12
// speedup vs baseline: 1.2487x; 1.0349x over previous
#include <cuda_runtime.h>
#include <cuda_fp16.h>
#include <cstdint>

// ============================================================================
// Problem dims (fixed): x [4,2048,1024], E=8 experts, H=4096
// ============================================================================
static constexpr int NTOK = 8192;   // B*T
static constexpr int C    = 1024;
static constexpr int H    = 4096;
static constexpr int E    = 8;

static constexpr int BM = 128, BN = 64, BK = 64;
static constexpr int MAX_TILES = 72;    // sum ceil(cnt_e/BM) <= 64 + 7

// ============================================================================
// Scratch (static __device__ — no allocation allowed)
// ============================================================================
__device__ __half g_w1c[(size_t)E * C * H];   // fp16 copy of w1, [E][C][H] (K-major)
__device__ __half g_w2c[(size_t)E * H * C];   // fp16 copy of w2, [E][H][C] (K-major)
__device__ __half g_Xg [(size_t)NTOK * C];    // gathered tokens, fp16
__device__ __half g_Hg [(size_t)NTOK * H];    // hidden activations, fp16
__device__ int    g_top1[NTOK];
__device__ int    g_tokof[NTOK];
__device__ int    g_counts[E];
__device__ int    g_offsets[E];
__device__ int    g_cursors[E];
__device__ int    g_done;
__device__ int    g_ntiles;
__device__ int    g_tiles[MAX_TILES];          // (e << 16) | m_tile

#define DI __device__ __forceinline__

DI uint32_t smem_u32(const void* p) {
    uint32_t r;
    asm("{ .reg .u64 t; cvta.to.shared.u64 t, %1; cvt.u32.u64 %0, t; }"
        : "=r"(r) : "l"(p));
    return r;
}

// 16B async copy, zero-fill when srcsize==0
DI void cp16(uint32_t dst, const void* src, int srcsize) {
    asm volatile("cp.async.cg.shared.global [%0], [%1], 16, %2;"
                 :: "r"(dst), "l"(src), "r"(srcsize) : "memory");
}
#define CP_COMMIT() asm volatile("cp.async.commit_group;" ::: "memory")
#define CP_WAIT(n)  asm volatile("cp.async.wait_group %0;" :: "n"(n) : "memory")

DI void ldsm4(uint32_t* r, uint32_t addr) {
    asm volatile("ldmatrix.sync.aligned.m8n8.x4.shared.b16 {%0,%1,%2,%3}, [%4];"
                 : "=r"(r[0]), "=r"(r[1]), "=r"(r[2]), "=r"(r[3]) : "r"(addr));
}

DI void ldsm4t(uint32_t* r, uint32_t addr) {
    asm volatile("ldmatrix.sync.aligned.m8n8.x4.trans.shared.b16 {%0,%1,%2,%3}, [%4];"
                 : "=r"(r[0]), "=r"(r[1]), "=r"(r[2]), "=r"(r[3]) : "r"(addr));
}

DI void mma16816(float* d, const uint32_t* a, uint32_t b0, uint32_t b1) {
    asm volatile(
        "mma.sync.aligned.m16n8k16.row.col.f32.f16.f16.f32 "
        "{%0,%1,%2,%3}, {%4,%5,%6,%7}, {%8,%9}, {%0,%1,%2,%3};"
        : "+f"(d[0]), "+f"(d[1]), "+f"(d[2]), "+f"(d[3])
        : "r"(a[0]), "r"(a[1]), "r"(a[2]), "r"(a[3]), "r"(b0), "r"(b1));
}

// 128B tile rows (64 halves), 8x16B chunks, chunk ^= row&7 -> conflict-free
// for cp.async stores and both ldmatrix variants. Used for A and B tiles.
DI uint32_t swz(int row, int chunk) {
    return (uint32_t)(row * 128 + ((chunk ^ (row & 7)) << 4));
}

// ============================================================================
// Stage 1: setup kernels
// ============================================================================

// Streaming fp32 -> fp16 convert of BOTH weight tensors (layout preserved).
__global__ void k_convert(const float* __restrict__ w1, const float* __restrict__ w2,
                          __half* __restrict__ w1c, __half* __restrict__ w2c,
                          int n4) {
    if (blockIdx.x == 0 && threadIdx.x <= E) {
        if (threadIdx.x < E) g_counts[threadIdx.x] = 0;
        else                 g_done = 0;
    }
    const int stride = gridDim.x * blockDim.x;
    for (int i = blockIdx.x * blockDim.x + threadIdx.x; i < 2 * n4; i += stride) {
        const bool second = (i >= n4);
        const int idx = second ? i - n4 : i;
        const float4 v = reinterpret_cast<const float4*>(second ? w2 : w1)[idx];
        __half2 h0 = __floats2half2_rn(v.x, v.y);
        __half2 h1 = __floats2half2_rn(v.z, v.w);
        uint2 pk;
        pk.x = *reinterpret_cast<uint32_t*>(&h0);
        pk.y = *reinterpret_cast<uint32_t*>(&h1);
        reinterpret_cast<uint2*>(second ? w2c : w1c)[idx] = pk;
    }
}

// Router + histogram + (last block) scan + tile table.
__global__ void k_router(const float* __restrict__ x,
                         const float* __restrict__ wr,
                         const float* __restrict__ br) {
    __shared__ int loc[E];
    if (threadIdx.x < E) loc[threadIdx.x] = 0;
    __syncthreads();
    const int wid = threadIdx.x >> 5, lane = threadIdx.x & 31;
    const int t = blockIdx.x * 8 + wid;
    const float* xr = x + (size_t)t * C;
    float acc[8] = {0.f, 0.f, 0.f, 0.f, 0.f, 0.f, 0.f, 0.f};
    for (int c = lane; c < C; c += 32) {
        const float xv = xr[c];
        const float4* w4 = reinterpret_cast<const float4*>(wr + (size_t)c * E);
        const float4 a = w4[0], b = w4[1];
        acc[0] += xv * a.x; acc[1] += xv * a.y; acc[2] += xv * a.z; acc[3] += xv * a.w;
        acc[4] += xv * b.x; acc[5] += xv * b.y; acc[6] += xv * b.z; acc[7] += xv * b.w;
    }
    #pragma unroll
    for (int j = 0; j < 8; j++)
        #pragma unroll
        for (int o = 16; o; o >>= 1)
            acc[j] += __shfl_xor_sync(0xFFFFFFFFu, acc[j], o);
    if (lane == 0) {
        float best = -1e30f; int bi = 0;
        #pragma unroll
        for (int j = 0; j < 8; j++) {
            const float v = acc[j] + br[j];
            if (v > best) { best = v; bi = j; }   // first-max, matches argmax
        }
        g_top1[t] = bi;
        atomicAdd(&loc[bi], 1);
    }
    __syncthreads();
    if (threadIdx.x < E) atomicAdd(&g_counts[threadIdx.x], loc[threadIdx.x]);
    __threadfence();
    __syncthreads();
    if (threadIdx.x == 0) {
        if (atomicAdd(&g_done, 1) == (int)gridDim.x - 1) {
            int s = 0, tt = 0;
            for (int e = 0; e < E; e++) {
                g_offsets[e] = s;
                g_cursors[e] = s;
                const int cnt = g_counts[e];
                for (int mt = 0; mt * BM < cnt; mt++)
                    g_tiles[tt++] = (e << 16) | mt;
                s += cnt;
            }
            g_ntiles = tt;
            __threadfence();
        }
    }
}

// Fused map + gather: block per token; claim slot, copy fp32 row -> fp16.
__global__ void k_mapgather(const float* __restrict__ x) {
    const int t = blockIdx.x;
    __shared__ int rs;
    if (threadIdx.x == 0) {
        const int e = g_top1[t];
        const int pos = atomicAdd(&g_cursors[e], 1);
        g_tokof[pos] = t;
        rs = pos;
    }
    __syncthreads();
    const int r = rs;
    const float4 v = reinterpret_cast<const float4*>(x + (size_t)t * C)[threadIdx.x];
    __half2* dst = reinterpret_cast<__half2*>(g_Xg + (size_t)r * C) + threadIdx.x * 2;
    dst[0] = __floats2half2_rn(v.x, v.y);
    dst[1] = __floats2half2_rn(v.z, v.w);
}

// ============================================================================
// Stage 2: grouped GEMM via mma.sync (HMMA, fp16 in / fp32 accum)
//   PHASE1: Hg = gelu(Xg @ w1[e] + b1[e])    (M=cnt, N=4096, K=1024)
//   PHASE2: out[tok] = Hg @ w2[e] + b2[e]    (M=cnt, N=1024, K=4096)
// A: [M][K] rows (ldmatrix), B: [K][N] K-major rows (ldmatrix.trans).
// BM=128, BN=64, BK=64. 8 warps (4x2 grid, 32x32 warp tile), 3-stage
// cp.async, one __syncthreads per K-chunk, 3 CTAs/SM (24 warps).
// ============================================================================
static constexpr int A_TILE_B = BM * BK * 2;              // 16 KB
static constexpr int B_TILE_B = BK * BN * 2;              //  8 KB
static constexpr int STAGE_B  = A_TILE_B + B_TILE_B;      // 24 KB
static constexpr int NSTAGE   = 3;
static constexpr int GEMM_SMEM = NSTAGE * STAGE_B;        // 72 KB

template<bool PHASE1>
__global__ void __launch_bounds__(256, 3)
moe_gemm(const float* __restrict__ bias, float* __restrict__ out) {
    constexpr int KT = PHASE1 ? C : H;
    constexpr int NT = PHASE1 ? H : C;
    constexpr int NK = KT / BK;

    extern __shared__ __align__(1024) char smem[];

    if ((int)blockIdx.y >= g_ntiles) return;
    const int pk  = g_tiles[blockIdx.y];
    const int e   = pk >> 16;
    const int m0  = (pk & 0xFFFF) * BM;
    const int cnt = g_counts[e];

    const int tid  = threadIdx.x;
    const int wid  = tid >> 5, lane = tid & 31;
    const int wm   = wid >> 1, wn = wid & 1;      // 4 x 2 warp grid (32x32)
    const int base = g_offsets[e];
    const int valid = min(BM, cnt - m0);
    const int n0   = blockIdx.x * BN;

    const __half* Ag = (PHASE1 ? g_Xg : g_Hg) + (size_t)(base + m0) * KT;
    const __half* Bg = (PHASE1 ? g_w1c : g_w2c) + (size_t)e * KT * NT + n0;
    const uint32_t sb = smem_u32(smem);

    // loader mapping: rows (tid>>3)+32h, 16B chunk gc (8 per 128B row)
    const int gr = tid >> 3, gc = tid & 7;

    auto issue = [&](int kc, int st) {
        const uint32_t As = sb + (uint32_t)st * STAGE_B;
        const uint32_t Bs = As + A_TILE_B;
        #pragma unroll
        for (int h = 0; h < 4; h++) {             // A: 128 rows x 128B
            const int row = gr + h * 32;
            const int rA = (row < valid) ? row : 0;
            cp16(As + swz(row, gc), Ag + (size_t)rA * KT + kc * BK + gc * 8,
                 (row < valid) ? 16 : 0);
        }
        #pragma unroll
        for (int h = 0; h < 2; h++) {             // B: 64 K-rows x 128B (BN=64)
            const int krow = gr + h * 32;
            cp16(Bs + swz(krow, gc),
                 Bg + (size_t)(kc * BK + krow) * NT + gc * 8, 16);
        }
        CP_COMMIT();
    };

    const int l15 = lane & 15, hi = lane >> 4;

    float acc[2][4][4];
    #pragma unroll
    for (int i = 0; i < 2; i++)
        #pragma unroll
        for (int j = 0; j < 4; j++)
            #pragma unroll
            for (int k = 0; k < 4; k++) acc[i][j][k] = 0.f;

    issue(0, 0);
    issue(1, 1);
    int ist = 2, cst = 0;
    for (int kc = 0; kc < NK; kc++) {
        if (kc + 1 < NK) { CP_WAIT(1); } else { CP_WAIT(0); }
        __syncthreads();
        if (kc + 2 < NK) {
            issue(kc + 2, ist);
            ist = (ist + 1 == NSTAGE) ? 0 : ist + 1;
        }

        const uint32_t As = sb + (uint32_t)cst * STAGE_B;
        const uint32_t Bs = As + A_TILE_B;
        cst = (cst + 1 == NSTAGE) ? 0 : cst + 1;

        #pragma unroll
        for (int s = 0; s < 4; s++) {             // 4 x k16 phases per chunk
            uint32_t a[2][4], b[2][4];
            const int ch = s * 2 + hi;
            #pragma unroll
            for (int i = 0; i < 2; i++) {
                const int row = wm * 32 + i * 16 + l15;
                ldsm4(a[i], As + swz(row, ch));
            }
            const int krow = s * 16 + l15;
            #pragma unroll
            for (int jj = 0; jj < 2; jj++) {
                const int ncol = wn * 32 + jj * 16 + hi * 8;
                ldsm4t(b[jj], Bs + swz(krow, ncol >> 3));
            }
            #pragma unroll
            for (int i = 0; i < 2; i++)
                #pragma unroll
                for (int j = 0; j < 4; j++) {
                    const int jj = j >> 1, f = j & 1;
                    mma16816(acc[i][j], a[i], b[jj][f * 2], b[jj][f * 2 + 1]);
                }
        }
    }

    // Epilogue: thread holds rows {g, g+8} of each 16-row frag, cols 2q,2q+1
    const int g = lane >> 2, q = lane & 3;
    const float* bp = bias + (size_t)e * NT;
    #pragma unroll
    for (int i = 0; i < 2; i++) {
        #pragma unroll
        for (int hr = 0; hr < 2; hr++) {
            const int row = wm * 32 + i * 16 + g + hr * 8;
            if (row >= valid) continue;
            #pragma unroll
            for (int j = 0; j < 4; j++) {
                const int col = n0 + wn * 32 + j * 8 + q * 2;
                float v0 = acc[i][j][hr * 2 + 0] + bp[col];
                float v1 = acc[i][j][hr * 2 + 1] + bp[col + 1];
                if (PHASE1) {
                    v0 = 0.5f * v0 * (1.0f + erff(v0 * 0.70710678118654752f));
                    v1 = 0.5f * v1 * (1.0f + erff(v1 * 0.70710678118654752f));
                    *reinterpret_cast<__half2*>(
                        g_Hg + (size_t)(base + m0 + row) * H + col) =
                        __floats2half2_rn(v0, v1);
                } else {
                    const int tok = g_tokof[base + m0 + row];
                    float2 v; v.x = v0; v.y = v1;
                    *reinterpret_cast<float2*>(
                        out + (size_t)tok * C + col) = v;
                }
            }
        }
    }
}

// ============================================================================
// kernel_launch  (GEMM1 is OUR launch #4)
// ============================================================================
extern "C" void kernel_launch(void* const* d_in, const int* in_sizes, int n_in,
                              void* d_out, int out_size) {
    const float* x  = (const float*)d_in[0];
    const float* wr = (const float*)d_in[1];
    const float* br = (const float*)d_in[2];
    const float* w1 = (const float*)d_in[3];
    const float* b1 = (const float*)d_in[4];
    const float* w2 = (const float*)d_in[5];
    const float* b2 = (const float*)d_in[6];
    float* out = (float*)d_out;

    cudaFuncSetAttribute(moe_gemm<true>,
                         cudaFuncAttributeMaxDynamicSharedMemorySize, GEMM_SMEM);
    cudaFuncSetAttribute(moe_gemm<false>,
                         cudaFuncAttributeMaxDynamicSharedMemorySize, GEMM_SMEM);

    constexpr int N4 = (E * C * H) / 4;          // 8.39M float4s per weight tensor
    __half* w1c; cudaGetSymbolAddress((void**)&w1c, g_w1c);
    __half* w2c; cudaGetSymbolAddress((void**)&w2c, g_w2c);

    k_convert<<<4096, 256>>>(w1, w2, w1c, w2c, N4);   // #1 (+zero counters)
    k_router<<<NTOK / 8, 256>>>(x, wr, br);            // #2 (+count +scan +tiles)
    k_mapgather<<<NTOK, 256>>>(x);                     // #3
    moe_gemm<true><<<dim3(H / BN, MAX_TILES), 256, GEMM_SMEM>>>(b1, nullptr);  // #4
    moe_gemm<false><<<dim3(C / BN, MAX_TILES), 256, GEMM_SMEM>>>(b2, out);     // #5
}